// round 1
// baseline (speedup 1.0000x reference)
#include <cuda_runtime.h>
#include <math.h>

#define D     128
#define KP    20
#define OUTD  128
#define VMAX  100000
#define EMAX  400000
#define EPS   1e-5f

// ---------------- scratch (device globals; no allocations) ----------------
__device__ float g_npj  [VMAX * KP];
__device__ float g_logit[EMAX];
__device__ float g_aexp [EMAX];
__device__ float g_lmax [VMAX];
__device__ float g_asum [VMAX];
__device__ float g_hv   [VMAX * D];
__device__ float g_ctx  [VMAX * D];
__device__ float g_kf   [VMAX * OUTD];
__device__ float g_gi   [VMAX * 3 * D];
__device__ float g_gh   [VMAX * 3 * D];
__device__ float g_gru  [VMAX * D];
__device__ float g_WihT [D * 3 * D];
__device__ float g_WhhT [D * 3 * D];

// ---------------- utility kernels ----------------
__global__ void zero_kernel(float4* p, int n4) {
    int i = blockIdx.x * blockDim.x + threadIdx.x;
    if (i < n4) p[i] = make_float4(0.f, 0.f, 0.f, 0.f);
}

// WihT[k*384+o] = Wih[o*128+k]  (and same for Whh)
__global__ void transpose_kernel(const float* __restrict__ Wih,
                                 const float* __restrict__ Whh) {
    int idx = blockIdx.x * blockDim.x + threadIdx.x;   // over 384*128
    if (idx >= 3 * D * D) return;
    int o = idx / D;
    int k = idx % D;
    g_WihT[k * (3 * D) + o] = Wih[idx];
    g_WhhT[k * (3 * D) + o] = Whh[idx];
}

// ---------------- npj = relu(LN(x @ Wk1 + bk1)), [V,20] ----------------
__global__ void npj_kernel(const float* __restrict__ x,
                           const float* __restrict__ Wk1,
                           const float* __restrict__ bk1,
                           const float* __restrict__ g,
                           const float* __restrict__ b, int V) {
    __shared__ float xs[4][D];
    int warp = threadIdx.x >> 5, lane = threadIdx.x & 31;
    int v  = blockIdx.x * 4 + warp;
    int vc = v < V ? v : V - 1;
    *(float4*)&xs[warp][lane << 2] = *(const float4*)&x[vc * D + (lane << 2)];
    __syncwarp();
    float y = 0.f;
    if (lane < KP) {
        #pragma unroll 8
        for (int k = 0; k < D; k++) y = fmaf(xs[warp][k], Wk1[k * KP + lane], y);
        y += bk1[lane];
    }
    float s = (lane < KP) ? y : 0.f;
    #pragma unroll
    for (int m = 16; m; m >>= 1) s += __shfl_xor_sync(0xffffffffu, s, m);
    float mu = s * (1.f / KP);
    float dv = (lane < KP) ? (y - mu) * (y - mu) : 0.f;
    #pragma unroll
    for (int m = 16; m; m >>= 1) dv += __shfl_xor_sync(0xffffffffu, dv, m);
    float rstd = rsqrtf(dv * (1.f / KP) + EPS);
    if (v < V && lane < KP) {
        float val = (y - mu) * rstd * g[lane] + b[lane];
        g_npj[v * KP + lane] = fmaxf(val, 0.f);
    }
}

// ---------------- edge logits + segment max ----------------
__global__ void logits_kernel(const float* __restrict__ x,
                              const int* __restrict__ src,
                              const int* __restrict__ dst,
                              const float* __restrict__ We,
                              const float* __restrict__ be, int E) {
    int e = blockIdx.x * 4 + (threadIdx.x >> 5);
    if (e >= E) return;
    int lane = threadIdx.x & 31;
    int sn = src[e], dn = dst[e];
    float4 xd = *(const float4*)&x[dn * D + (lane << 2)];
    float4 w1 = *(const float4*)&We[lane << 2];
    float4 xv = *(const float4*)&x[sn * D + (lane << 2)];
    float4 w2 = *(const float4*)&We[D + (lane << 2)];
    float p = xd.x * w1.x + xd.y * w1.y + xd.z * w1.z + xd.w * w1.w
            + xv.x * w2.x + xv.y * w2.y + xv.z * w2.z + xv.w * w2.w;
    #pragma unroll
    for (int m = 16; m; m >>= 1) p += __shfl_xor_sync(0xffffffffu, p, m);
    if (lane == 0) {
        float lg = fmaxf(p + be[0], 0.f);
        g_logit[e] = lg;
        atomicMax((int*)&g_lmax[dn], __float_as_int(lg));  // valid: lg >= 0
    }
}

// ---------------- a = exp(logit - lmax[dst]); asum += a ----------------
__global__ void expsum_kernel(const int* __restrict__ dst, int E) {
    int e = blockIdx.x * blockDim.x + threadIdx.x;
    if (e >= E) return;
    int dn = dst[e];
    float a = expf(g_logit[e] - g_lmax[dn]);
    g_aexp[e] = a;
    atomicAdd(&g_asum[dn], a);
}

// ---------------- context scatter: ctx[dst] += hv[src] * (a/asum[dst]) ----
__global__ void context_kernel(const int* __restrict__ src,
                               const int* __restrict__ dst, int E) {
    int e = blockIdx.x * 4 + (threadIdx.x >> 5);
    if (e >= E) return;
    int lane = threadIdx.x & 31;
    int sn = src[e], dn = dst[e];
    float coef = g_aexp[e] / g_asum[dn];
    float4 h = *(const float4*)&g_hv[sn * D + (lane << 2)];
    float* p = &g_ctx[dn * D + (lane << 2)];
    atomicAdd(p + 0, h.x * coef);
    atomicAdd(p + 1, h.y * coef);
    atomicAdd(p + 2, h.z * coef);
    atomicAdd(p + 3, h.w * coef);
}

// ---------------- generic node GEMM: out = [X0|X1] @ W + bias (opt LN+relu)
#define BM 64
#define BK 32
__global__ void gemm_kernel(const float* __restrict__ X0, int K0,
                            const float* __restrict__ X1, int K1,
                            int relu_in,
                            const float* __restrict__ W, int Ntot,
                            const float* __restrict__ bias,
                            const float* __restrict__ lng,
                            const float* __restrict__ lnb,
                            float* __restrict__ out, int V) {
    __shared__ float Xs[BM][BK + 4];
    __shared__ float Ws[BK][128];
    int tid = threadIdx.x;
    int tx = tid & 31, ty = tid >> 5;
    int row0 = blockIdx.x * BM;
    int ob = blockIdx.y * 128;
    int K = K0 + K1;
    float acc[8][4];
    #pragma unroll
    for (int e = 0; e < 8; e++) { acc[e][0]=acc[e][1]=acc[e][2]=acc[e][3]=0.f; }

    for (int kb = 0; kb < K; kb += BK) {
        #pragma unroll
        for (int i = 0; i < 2; i++) {
            int idx = tid + i * 256;          // 512 float4s
            int r = idx >> 3, k4 = (idx & 7) << 2;
            int grow = row0 + r; if (grow >= V) grow = V - 1;
            int gk = kb + k4;
            float4 v;
            if (gk < K0) v = *(const float4*)&X0[(size_t)grow * K0 + gk];
            else         v = *(const float4*)&X1[(size_t)grow * K1 + (gk - K0)];
            if (relu_in) { v.x=fmaxf(v.x,0.f); v.y=fmaxf(v.y,0.f);
                           v.z=fmaxf(v.z,0.f); v.w=fmaxf(v.w,0.f); }
            *(float4*)&Xs[r][k4] = v;
        }
        #pragma unroll
        for (int i = 0; i < 4; i++) {
            int idx = tid + i * 256;          // 1024 float4s
            int k = idx >> 5, o4 = (idx & 31) << 2;
            *(float4*)&Ws[k][o4] = *(const float4*)&W[(size_t)(kb + k) * Ntot + ob + o4];
        }
        __syncthreads();
        #pragma unroll 8
        for (int k = 0; k < BK; k++) {
            float4 w = *(float4*)&Ws[k][tx << 2];
            #pragma unroll
            for (int e = 0; e < 8; e++) {
                float xv = Xs[ty * 8 + e][k];
                acc[e][0] = fmaf(xv, w.x, acc[e][0]);
                acc[e][1] = fmaf(xv, w.y, acc[e][1]);
                acc[e][2] = fmaf(xv, w.z, acc[e][2]);
                acc[e][3] = fmaf(xv, w.w, acc[e][3]);
            }
        }
        __syncthreads();
    }

    float4 bv = *(const float4*)&bias[ob + (tx << 2)];
    #pragma unroll
    for (int e = 0; e < 8; e++) {
        acc[e][0]+=bv.x; acc[e][1]+=bv.y; acc[e][2]+=bv.z; acc[e][3]+=bv.w;
    }

    if (lng == nullptr) {
        #pragma unroll
        for (int e = 0; e < 8; e++) {
            int r = row0 + ty * 8 + e;
            if (r < V)
                *(float4*)&out[(size_t)r * Ntot + ob + (tx << 2)] =
                    make_float4(acc[e][0], acc[e][1], acc[e][2], acc[e][3]);
        }
    } else {  // LN + relu epilogue (Ntot==128, gridDim.y==1)
        float4 gv = *(const float4*)&lng[tx << 2];
        float4 b2 = *(const float4*)&lnb[tx << 2];
        #pragma unroll
        for (int e = 0; e < 8; e++) {
            float s = acc[e][0] + acc[e][1] + acc[e][2] + acc[e][3];
            #pragma unroll
            for (int m = 16; m; m >>= 1) s += __shfl_xor_sync(0xffffffffu, s, m);
            float mu = s * (1.f / 128.f);
            float q = 0.f;
            #pragma unroll
            for (int i = 0; i < 4; i++) { float d0 = acc[e][i] - mu; q = fmaf(d0, d0, q); }
            #pragma unroll
            for (int m = 16; m; m >>= 1) q += __shfl_xor_sync(0xffffffffu, q, m);
            float rstd = rsqrtf(q * (1.f / 128.f) + EPS);
            float4 o;
            o.x = fmaxf((acc[e][0] - mu) * rstd * gv.x + b2.x, 0.f);
            o.y = fmaxf((acc[e][1] - mu) * rstd * gv.y + b2.y, 0.f);
            o.z = fmaxf((acc[e][2] - mu) * rstd * gv.z + b2.z, 0.f);
            o.w = fmaxf((acc[e][3] - mu) * rstd * gv.w + b2.w, 0.f);
            int r = row0 + ty * 8 + e;
            if (r < V) *(float4*)&out[(size_t)r * 128 + (tx << 2)] = o;
        }
    }
}

// ---------------- edge Kronecker GEMM + LN + relu + scatter ----------------
__global__ void kron_kernel(const int* __restrict__ src,
                            const int* __restrict__ dst,
                            const float* __restrict__ Wk2,
                            const float* __restrict__ bk2,
                            const float* __restrict__ lng,
                            const float* __restrict__ lnb, int E) {
    __shared__ float Ss[64][KP];
    __shared__ float Ds[64][KP];
    __shared__ float Ws[KP][128];
    __shared__ int s_src[64], s_dst[64];
    int tid = threadIdx.x;
    int tx = tid & 31, ty = tid >> 5;
    int e0 = blockIdx.x * 64;

    if (tid < 64) {
        int ee = e0 + tid; if (ee >= E) ee = E - 1;
        s_src[tid] = src[ee];
        s_dst[tid] = dst[ee];
    }
    __syncthreads();
    for (int idx = tid; idx < 64 * KP; idx += 256) {
        int e = idx / KP, j = idx % KP;
        Ss[e][j] = g_npj[s_src[e] * KP + j];
        Ds[e][j] = g_npj[s_dst[e] * KP + j];
    }

    float acc[8][4];
    #pragma unroll
    for (int e = 0; e < 8; e++) { acc[e][0]=acc[e][1]=acc[e][2]=acc[e][3]=0.f; }

    for (int i = 0; i < KP; i++) {
        __syncthreads();
        for (int idx = tid; idx < 640; idx += 256) {   // 20*128 floats as float4
            int j = idx >> 5, o4 = (idx & 31) << 2;
            *(float4*)&Ws[j][o4] = *(const float4*)&Wk2[(i * KP + j) * 128 + o4];
        }
        __syncthreads();
        float sv[8];
        #pragma unroll
        for (int e = 0; e < 8; e++) sv[e] = Ss[ty * 8 + e][i];
        #pragma unroll 4
        for (int j = 0; j < KP; j++) {
            float4 w = *(float4*)&Ws[j][tx << 2];
            #pragma unroll
            for (int e = 0; e < 8; e++) {
                float p = sv[e] * Ds[ty * 8 + e][j];
                acc[e][0] = fmaf(p, w.x, acc[e][0]);
                acc[e][1] = fmaf(p, w.y, acc[e][1]);
                acc[e][2] = fmaf(p, w.z, acc[e][2]);
                acc[e][3] = fmaf(p, w.w, acc[e][3]);
            }
        }
    }

    float4 bv = *(const float4*)&bk2[tx << 2];
    float4 gv = *(const float4*)&lng[tx << 2];
    float4 b2 = *(const float4*)&lnb[tx << 2];
    #pragma unroll
    for (int e = 0; e < 8; e++) {
        acc[e][0]+=bv.x; acc[e][1]+=bv.y; acc[e][2]+=bv.z; acc[e][3]+=bv.w;
        float s = acc[e][0] + acc[e][1] + acc[e][2] + acc[e][3];
        #pragma unroll
        for (int m = 16; m; m >>= 1) s += __shfl_xor_sync(0xffffffffu, s, m);
        float mu = s * (1.f / 128.f);
        float q = 0.f;
        #pragma unroll
        for (int i = 0; i < 4; i++) { float d0 = acc[e][i] - mu; q = fmaf(d0, d0, q); }
        #pragma unroll
        for (int m = 16; m; m >>= 1) q += __shfl_xor_sync(0xffffffffu, q, m);
        float rstd = rsqrtf(q * (1.f / 128.f) + EPS);
        int le = ty * 8 + e;
        int ge = e0 + le;
        if (ge < E) {
            int dn = s_dst[le];
            float* p = &g_kf[dn * 128 + (tx << 2)];
            atomicAdd(p + 0, fmaxf((acc[e][0]-mu)*rstd*gv.x + b2.x, 0.f));
            atomicAdd(p + 1, fmaxf((acc[e][1]-mu)*rstd*gv.y + b2.y, 0.f));
            atomicAdd(p + 2, fmaxf((acc[e][2]-mu)*rstd*gv.z + b2.z, 0.f));
            atomicAdd(p + 3, fmaxf((acc[e][3]-mu)*rstd*gv.w + b2.w, 0.f));
        }
    }
}

// ---------------- GRU gates + relu + LN ----------------
__global__ void gates_kernel(const float* __restrict__ x,
                             const float* __restrict__ lng,
                             const float* __restrict__ lnb, int V) {
    int v = blockIdx.x * 4 + (threadIdx.x >> 5);
    if (v >= V) return;
    int lane = threadIdx.x & 31;
    const float* gi = &g_gi[(size_t)v * 384];
    const float* gh = &g_gh[(size_t)v * 384];
    float4 gir = *(const float4*)&gi[(lane << 2)];
    float4 giz = *(const float4*)&gi[128 + (lane << 2)];
    float4 gin = *(const float4*)&gi[256 + (lane << 2)];
    float4 ghr = *(const float4*)&gh[(lane << 2)];
    float4 ghz = *(const float4*)&gh[128 + (lane << 2)];
    float4 ghn = *(const float4*)&gh[256 + (lane << 2)];
    float4 xv  = *(const float4*)&x[(size_t)v * D + (lane << 2)];
    float h[4];
    #pragma unroll
    for (int i = 0; i < 4; i++) {
        float a_r = (&gir.x)[i] + (&ghr.x)[i];
        float a_z = (&giz.x)[i] + (&ghz.x)[i];
        float r = 1.f / (1.f + expf(-a_r));
        float z = 1.f / (1.f + expf(-a_z));
        float n = tanhf((&gin.x)[i] + r * (&ghn.x)[i]);
        float hh = (1.f - z) * n + z * (&xv.x)[i];
        h[i] = fmaxf(hh, 0.f);
    }
    float s = h[0] + h[1] + h[2] + h[3];
    #pragma unroll
    for (int m = 16; m; m >>= 1) s += __shfl_xor_sync(0xffffffffu, s, m);
    float mu = s * (1.f / 128.f);
    float q = 0.f;
    #pragma unroll
    for (int i = 0; i < 4; i++) { float d0 = h[i] - mu; q = fmaf(d0, d0, q); }
    #pragma unroll
    for (int m = 16; m; m >>= 1) q += __shfl_xor_sync(0xffffffffu, q, m);
    float rstd = rsqrtf(q * (1.f / 128.f) + EPS);
    float4 gv = *(const float4*)&lng[lane << 2];
    float4 b2 = *(const float4*)&lnb[lane << 2];
    float4 o;
    o.x = (h[0] - mu) * rstd * gv.x + b2.x;
    o.y = (h[1] - mu) * rstd * gv.y + b2.y;
    o.z = (h[2] - mu) * rstd * gv.z + b2.z;
    o.w = (h[3] - mu) * rstd * gv.w + b2.w;
    *(float4*)&g_gru[(size_t)v * D + (lane << 2)] = o;
}

// ---------------- host ----------------
extern "C" void kernel_launch(void* const* d_in, const int* in_sizes, int n_in,
                              void* d_out, int out_size) {
    const float* node   = (const float*)d_in[0];
    const int*   src    = (const int*)  d_in[1];
    const int*   dst    = (const int*)  d_in[2];
    const float* W_edge = (const float*)d_in[3];
    const float* b_edge = (const float*)d_in[4];
    const float* W_pn   = (const float*)d_in[5];
    const float* b_pn   = (const float*)d_in[6];
    const float* W_ih   = (const float*)d_in[7];
    const float* b_ih   = (const float*)d_in[8];
    const float* W_hh   = (const float*)d_in[9];
    const float* b_hh   = (const float*)d_in[10];
    const float* ln_g   = (const float*)d_in[11];
    const float* ln_b   = (const float*)d_in[12];
    const float* Wk1    = (const float*)d_in[13];
    const float* bk1    = (const float*)d_in[14];
    const float* lnk1_g = (const float*)d_in[15];
    const float* lnk1_b = (const float*)d_in[16];
    const float* Wk2    = (const float*)d_in[17];
    const float* bk2    = (const float*)d_in[18];
    const float* lnk2_g = (const float*)d_in[19];
    const float* lnk2_b = (const float*)d_in[20];
    const float* Wc     = (const float*)d_in[21];
    const float* bc     = (const float*)d_in[22];
    const float* lnc_g  = (const float*)d_in[23];
    const float* lnc_b  = (const float*)d_in[24];
    int V = in_sizes[0] / D;
    int E = in_sizes[1];
    float* out = (float*)d_out;

    float *p_ctx, *p_kf, *p_asum, *p_lmax, *p_hv, *p_gi, *p_gh, *p_gru, *p_WihT, *p_WhhT;
    cudaGetSymbolAddress((void**)&p_ctx,  g_ctx);
    cudaGetSymbolAddress((void**)&p_kf,   g_kf);
    cudaGetSymbolAddress((void**)&p_asum, g_asum);
    cudaGetSymbolAddress((void**)&p_lmax, g_lmax);
    cudaGetSymbolAddress((void**)&p_hv,   g_hv);
    cudaGetSymbolAddress((void**)&p_gi,   g_gi);
    cudaGetSymbolAddress((void**)&p_gh,   g_gh);
    cudaGetSymbolAddress((void**)&p_gru,  g_gru);
    cudaGetSymbolAddress((void**)&p_WihT, g_WihT);
    cudaGetSymbolAddress((void**)&p_WhhT, g_WhhT);

    // zero accumulators
    {
        int n4;
        n4 = V * D / 4;
        zero_kernel<<<(n4 + 255) / 256, 256>>>((float4*)p_ctx, n4);
        zero_kernel<<<(n4 + 255) / 256, 256>>>((float4*)p_kf,  n4);
        n4 = V / 4;
        zero_kernel<<<(n4 + 255) / 256, 256>>>((float4*)p_asum, n4);
        zero_kernel<<<(n4 + 255) / 256, 256>>>((float4*)p_lmax, n4);
    }
    transpose_kernel<<<(3 * D * D + 255) / 256, 256>>>(W_ih, W_hh);

    npj_kernel<<<(V + 3) / 4, 128>>>(node, Wk1, bk1, lnk1_g, lnk1_b, V);
    logits_kernel<<<(E + 3) / 4, 128>>>(node, src, dst, W_edge, b_edge, E);
    expsum_kernel<<<(E + 255) / 256, 256>>>(dst, E);

    // hv = node @ W_pn + b_pn
    gemm_kernel<<<dim3((V + BM - 1) / BM, 1), 256>>>(
        node, D, nullptr, 0, 0, W_pn, D, b_pn, nullptr, nullptr, p_hv, V);

    kron_kernel<<<(E + 63) / 64, 256>>>(src, dst, Wk2, bk2, lnk2_g, lnk2_b, E);
    context_kernel<<<(E + 3) / 4, 128>>>(src, dst, E);

    // gi = relu(ctx) @ WihT + b_ih ; gh = node @ WhhT + b_hh
    gemm_kernel<<<dim3((V + BM - 1) / BM, 3), 256>>>(
        p_ctx, D, nullptr, 0, 1, p_WihT, 3 * D, b_ih, nullptr, nullptr, p_gi, V);
    gemm_kernel<<<dim3((V + BM - 1) / BM, 3), 256>>>(
        node, D, nullptr, 0, 0, p_WhhT, 3 * D, b_hh, nullptr, nullptr, p_gh, V);

    gates_kernel<<<(V + 3) / 4, 128>>>(node, ln_g, ln_b, V);

    // out = relu(LN(cat(gru, kron_feat) @ Wc + bc))
    gemm_kernel<<<dim3((V + BM - 1) / BM, 1), 256>>>(
        p_gru, D, p_kf, D, 0, Wc, D, bc, lnc_g, lnc_b, out, V);
}

// round 2
// speedup vs baseline: 1.4478x; 1.4478x over previous
#include <cuda_runtime.h>
#include <cuda_bf16.h>
#include <math.h>
#include <stdint.h>

#define D     128
#define KP    20
#define OUTD  128
#define VMAX  100000
#define EMAX  400000
#define EPS   1e-5f

// ---------------- scratch (device globals; no allocations) ----------------
__device__ float g_npj  [VMAX * KP];
__device__ float g_logit[EMAX];
__device__ float g_aexp [EMAX];
__device__ float g_lmax [VMAX];
__device__ float g_asum [VMAX];
__device__ float g_hv   [VMAX * D];
__device__ float g_ctx  [VMAX * D];
__device__ float g_kf   [VMAX * OUTD];
__device__ float g_gi   [VMAX * 3 * D];
__device__ float g_gh   [VMAX * 3 * D];
__device__ float g_gru  [VMAX * D];

// packed bf16 hi/lo weights: [K/2][N] as uint32 (low half = even k)
__device__ uint32_t g_WpnP[2][64 * 128];
__device__ uint32_t g_WihP[2][64 * 384];
__device__ uint32_t g_WhhP[2][64 * 384];
__device__ uint32_t g_WcP [2][128 * 128];
__device__ uint32_t g_Wk2P[2][200 * 128];

// ---------------- bf16 split helpers ----------------
__device__ __forceinline__ uint32_t pkbf(float a, float b) {
    unsigned short ha = __bfloat16_as_ushort(__float2bfloat16_rn(a));
    unsigned short hb = __bfloat16_as_ushort(__float2bfloat16_rn(b));
    return ((uint32_t)hb << 16) | (uint32_t)ha;
}
__device__ __forceinline__ float bflo(float a) {
    return a - __bfloat162float(__float2bfloat16_rn(a));
}

#define MMA_BF16(c, A, B) asm volatile( \
    "mma.sync.aligned.m16n8k16.row.col.f32.bf16.bf16.f32 " \
    "{%0,%1,%2,%3}, {%4,%5,%6,%7}, {%8,%9}, {%0,%1,%2,%3};\n" \
    : "+f"(c[0]), "+f"(c[1]), "+f"(c[2]), "+f"(c[3]) \
    : "r"(A.x), "r"(A.y), "r"(A.z), "r"(A.w), "r"(B.x), "r"(B.y))

// ---------------- utility kernels ----------------
__global__ void zero_kernel(float4* p, int n4) {
    int i = blockIdx.x * blockDim.x + threadIdx.x;
    if (i < n4) p[i] = make_float4(0.f, 0.f, 0.f, 0.f);
}

// pack W [K][N] row-major -> hi/lo [K/2][N]
__global__ void pack_w(const float* __restrict__ W, int K, int N,
                       uint32_t* __restrict__ hi, uint32_t* __restrict__ lo) {
    int idx = blockIdx.x * blockDim.x + threadIdx.x;
    int total = (K / 2) * N;
    if (idx >= total) return;
    int kp = idx / N, n = idx % N;
    float w0 = W[(2 * kp) * N + n];
    float w1 = W[(2 * kp + 1) * N + n];
    hi[idx] = pkbf(w0, w1);
    lo[idx] = pkbf(bflo(w0), bflo(w1));
}

// pack W stored [N][K] (out-major, e.g. W_ih [384][128]) -> hi/lo [K/2][N]
__global__ void pack_wt(const float* __restrict__ W, int N, int K,
                        uint32_t* __restrict__ hi, uint32_t* __restrict__ lo) {
    int idx = blockIdx.x * blockDim.x + threadIdx.x;
    int total = (K / 2) * N;
    if (idx >= total) return;
    int kp = idx / N, n = idx % N;
    float w0 = W[n * K + 2 * kp];
    float w1 = W[n * K + 2 * kp + 1];
    hi[idx] = pkbf(w0, w1);
    lo[idx] = pkbf(bflo(w0), bflo(w1));
}

// ---------------- npj = relu(LN(x @ Wk1 + bk1)), [V,20] ----------------
__global__ void npj_kernel(const float* __restrict__ x,
                           const float* __restrict__ Wk1,
                           const float* __restrict__ bk1,
                           const float* __restrict__ g,
                           const float* __restrict__ b, int V) {
    __shared__ float xs[4][D];
    int warp = threadIdx.x >> 5, lane = threadIdx.x & 31;
    int v  = blockIdx.x * 4 + warp;
    int vc = v < V ? v : V - 1;
    *(float4*)&xs[warp][lane << 2] = *(const float4*)&x[vc * D + (lane << 2)];
    __syncwarp();
    float y = 0.f;
    if (lane < KP) {
        #pragma unroll 8
        for (int k = 0; k < D; k++) y = fmaf(xs[warp][k], Wk1[k * KP + lane], y);
        y += bk1[lane];
    }
    float s = (lane < KP) ? y : 0.f;
    #pragma unroll
    for (int m = 16; m; m >>= 1) s += __shfl_xor_sync(0xffffffffu, s, m);
    float mu = s * (1.f / KP);
    float dv = (lane < KP) ? (y - mu) * (y - mu) : 0.f;
    #pragma unroll
    for (int m = 16; m; m >>= 1) dv += __shfl_xor_sync(0xffffffffu, dv, m);
    float rstd = rsqrtf(dv * (1.f / KP) + EPS);
    if (v < V && lane < KP) {
        float val = (y - mu) * rstd * g[lane] + b[lane];
        g_npj[v * KP + lane] = fmaxf(val, 0.f);
    }
}

// ---------------- edge logits + segment max ----------------
__global__ void logits_kernel(const float* __restrict__ x,
                              const int* __restrict__ src,
                              const int* __restrict__ dst,
                              const float* __restrict__ We,
                              const float* __restrict__ be, int E) {
    int e = blockIdx.x * 4 + (threadIdx.x >> 5);
    if (e >= E) return;
    int lane = threadIdx.x & 31;
    int sn = src[e], dn = dst[e];
    float4 xd = *(const float4*)&x[dn * D + (lane << 2)];
    float4 w1 = *(const float4*)&We[lane << 2];
    float4 xv = *(const float4*)&x[sn * D + (lane << 2)];
    float4 w2 = *(const float4*)&We[D + (lane << 2)];
    float p = xd.x * w1.x + xd.y * w1.y + xd.z * w1.z + xd.w * w1.w
            + xv.x * w2.x + xv.y * w2.y + xv.z * w2.z + xv.w * w2.w;
    #pragma unroll
    for (int m = 16; m; m >>= 1) p += __shfl_xor_sync(0xffffffffu, p, m);
    if (lane == 0) {
        float lg = fmaxf(p + be[0], 0.f);
        g_logit[e] = lg;
        atomicMax((int*)&g_lmax[dn], __float_as_int(lg));  // valid: lg >= 0
    }
}

// ---------------- a = exp(logit - lmax[dst]); asum += a ----------------
__global__ void expsum_kernel(const int* __restrict__ dst, int E) {
    int e = blockIdx.x * blockDim.x + threadIdx.x;
    if (e >= E) return;
    int dn = dst[e];
    float a = expf(g_logit[e] - g_lmax[dn]);
    g_aexp[e] = a;
    atomicAdd(&g_asum[dn], a);
}

// ---------------- context scatter: ctx[dst] += hv[src] * (a/asum[dst]) ----
__global__ void context_kernel(const int* __restrict__ src,
                               const int* __restrict__ dst, int E) {
    int e = blockIdx.x * 4 + (threadIdx.x >> 5);
    if (e >= E) return;
    int lane = threadIdx.x & 31;
    int sn = src[e], dn = dst[e];
    float coef = g_aexp[e] / g_asum[dn];
    float4 h = *(const float4*)&g_hv[sn * D + (lane << 2)];
    float* p = &g_ctx[dn * D + (lane << 2)];
    atomicAdd(p + 0, h.x * coef);
    atomicAdd(p + 1, h.y * coef);
    atomicAdd(p + 2, h.z * coef);
    atomicAdd(p + 3, h.w * coef);
}

// =====================================================================
// Generic node GEMM via mma.bf16, 3-pass split:
//   out = [X0|X1] @ W + bias, optional relu on input, optional LN+relu out.
// Block tile: M=64 rows x N=128 cols, K chunk 32. 256 threads (8 warps),
// warp = m16 x n64:  wm = w&3 (m-tile), wn = w>>2 (n half).
// Fragment-layout smem (no ldmatrix).
// =====================================================================
__global__ __launch_bounds__(256, 2)
void mma_gemm(const float* __restrict__ X0, int K0,
              const float* __restrict__ X1, int K1, int relu_in,
              const uint32_t* __restrict__ Whi, const uint32_t* __restrict__ Wlo,
              int Ntot,
              const float* __restrict__ bias,
              const float* __restrict__ lng, const float* __restrict__ lnb,
              float* __restrict__ out, int V) {
    __shared__ uint32_t sa[4096];   // hi [0,2048), lo [2048,4096): [4mt][2ks][32][4]
    __shared__ uint32_t sb[4096];   // hi [0,2048), lo [2048,4096): [16nt][2ks][32][2]
    __shared__ float red[2][64][2];

    int t = threadIdx.x;
    int lane = t & 31, w = t >> 5;
    int wm = w & 3, wn = w >> 2;
    int row0 = blockIdx.x * 64;
    int nb = blockIdx.y * 128;
    int K = K0 + K1;

    float acc[8][4];
    #pragma unroll
    for (int j = 0; j < 8; j++) { acc[j][0]=acc[j][1]=acc[j][2]=acc[j][3]=0.f; }

    int lr = t >> 2;        // loader row 0..63
    int kg = t & 3;         // 8-float group within 32-k chunk
    int grow = row0 + lr; if (grow >= V) grow = V - 1;

    for (int kb = 0; kb < K; kb += 32) {
        __syncthreads();
        // ---- A loader: 8 floats -> 4 bf16x2 pairs (hi & lo) ----
        {
            int gk = kb + kg * 8;
            float4 u0, u1;
            if (gk < K0) {
                const float* p = &X0[(size_t)grow * K0 + gk];
                u0 = *(const float4*)p; u1 = *(const float4*)(p + 4);
            } else {
                const float* p = &X1[(size_t)grow * K1 + (gk - K0)];
                u0 = *(const float4*)p; u1 = *(const float4*)(p + 4);
            }
            float v[8] = {u0.x,u0.y,u0.z,u0.w,u1.x,u1.y,u1.z,u1.w};
            if (relu_in) {
                #pragma unroll
                for (int i = 0; i < 8; i++) v[i] = fmaxf(v[i], 0.f);
            }
            int mt = lr >> 4;
            int kstep = kg >> 1;
            int ribase = (lr >> 3) & 1;
            int rik = (kg & 1) << 1;
            #pragma unroll
            for (int p = 0; p < 4; p++) {
                float x0 = v[2*p], x1 = v[2*p+1];
                int aln = ((lr & 7) << 2) + p;
                int ai = (((mt * 2 + kstep) * 32 + aln) << 2) + ribase + rik;
                sa[ai]        = pkbf(x0, x1);
                sa[2048 + ai] = pkbf(bflo(x0), bflo(x1));
            }
        }
        // ---- B loader: pre-packed pairs [K/2][Ntot] ----
        {
            int kprow = (kb >> 1);
            #pragma unroll
            for (int i = 0; i < 8; i++) {
                int idx = t + (i << 8);       // 0..2047
                int kp = idx >> 7;            // 0..15
                int n  = idx & 127;
                int gidx = (kprow + kp) * Ntot + nb + n;
                int nt = n >> 3, kstep = kp >> 3;
                int bln = ((n & 7) << 2) + (kp & 3);
                int ri = (kp >> 2) & 1;
                int bi = (((nt * 2 + kstep) * 32 + bln) << 1) + ri;
                sb[bi]        = Whi[gidx];
                sb[2048 + bi] = Wlo[gidx];
            }
        }
        __syncthreads();
        // ---- compute ----
        #pragma unroll
        for (int ks = 0; ks < 2; ks++) {
            uint4 ah = *(uint4*)&sa[(((wm * 2 + ks) * 32 + lane) << 2)];
            uint4 al = *(uint4*)&sa[2048 + (((wm * 2 + ks) * 32 + lane) << 2)];
            #pragma unroll
            for (int j = 0; j < 8; j++) {
                int nt = wn * 8 + j;
                uint2 bh = *(uint2*)&sb[(((nt * 2 + ks) * 32 + lane) << 1)];
                uint2 bl = *(uint2*)&sb[2048 + (((nt * 2 + ks) * 32 + lane) << 1)];
                MMA_BF16(acc[j], ah, bh);
                MMA_BF16(acc[j], ah, bl);
                MMA_BF16(acc[j], al, bh);
            }
        }
    }

    // ---- epilogue ----
    int rl = row0 + wm * 16 + (lane >> 2);
    int rh = rl + 8;
    #pragma unroll
    for (int j = 0; j < 8; j++) {
        int gc = nb + wn * 64 + j * 8 + ((lane & 3) << 1);
        float b0 = bias[gc], b1 = bias[gc + 1];
        acc[j][0] += b0; acc[j][1] += b1; acc[j][2] += b0; acc[j][3] += b1;
    }
    if (lng == nullptr) {
        #pragma unroll
        for (int j = 0; j < 8; j++) {
            int gc = nb + wn * 64 + j * 8 + ((lane & 3) << 1);
            if (rl < V) *(float2*)&out[(size_t)rl * Ntot + gc] = make_float2(acc[j][0], acc[j][1]);
            if (rh < V) *(float2*)&out[(size_t)rh * Ntot + gc] = make_float2(acc[j][2], acc[j][3]);
        }
    } else {
        // LN over 128 cols (Ntot==128, gridDim.y==1), then relu, then store
        float s_lo=0.f, q_lo=0.f, s_hi=0.f, q_hi=0.f;
        #pragma unroll
        for (int j = 0; j < 8; j++) {
            s_lo += acc[j][0] + acc[j][1];
            q_lo += acc[j][0]*acc[j][0] + acc[j][1]*acc[j][1];
            s_hi += acc[j][2] + acc[j][3];
            q_hi += acc[j][2]*acc[j][2] + acc[j][3]*acc[j][3];
        }
        #pragma unroll
        for (int m = 1; m <= 2; m <<= 1) {
            s_lo += __shfl_xor_sync(0xffffffffu, s_lo, m);
            q_lo += __shfl_xor_sync(0xffffffffu, q_lo, m);
            s_hi += __shfl_xor_sync(0xffffffffu, s_hi, m);
            q_hi += __shfl_xor_sync(0xffffffffu, q_hi, m);
        }
        int rloc = wm * 16 + (lane >> 2);
        if ((lane & 3) == 0) {
            red[wn][rloc][0] = s_lo;   red[wn][rloc][1] = q_lo;
            red[wn][rloc+8][0] = s_hi; red[wn][rloc+8][1] = q_hi;
        }
        __syncthreads();
        float ts_lo = s_lo + red[wn ^ 1][rloc][0];
        float tq_lo = q_lo + red[wn ^ 1][rloc][1];
        float ts_hi = s_hi + red[wn ^ 1][rloc + 8][0];
        float tq_hi = q_hi + red[wn ^ 1][rloc + 8][1];
        float mu_lo = ts_lo * (1.f/128.f);
        float mu_hi = ts_hi * (1.f/128.f);
        float rs_lo = rsqrtf(tq_lo * (1.f/128.f) - mu_lo*mu_lo + EPS);
        float rs_hi = rsqrtf(tq_hi * (1.f/128.f) - mu_hi*mu_hi + EPS);
        #pragma unroll
        for (int j = 0; j < 8; j++) {
            int gc = wn * 64 + j * 8 + ((lane & 3) << 1);
            float g0 = lng[gc], g1 = lng[gc+1];
            float bb0 = lnb[gc], bb1 = lnb[gc+1];
            if (rl < V) {
                float o0 = fmaxf((acc[j][0]-mu_lo)*rs_lo*g0 + bb0, 0.f);
                float o1 = fmaxf((acc[j][1]-mu_lo)*rs_lo*g1 + bb1, 0.f);
                *(float2*)&out[(size_t)rl * 128 + gc] = make_float2(o0, o1);
            }
            if (rh < V) {
                float o2 = fmaxf((acc[j][2]-mu_hi)*rs_hi*g0 + bb0, 0.f);
                float o3 = fmaxf((acc[j][3]-mu_hi)*rs_hi*g1 + bb1, 0.f);
                *(float2*)&out[(size_t)rh * 128 + gc] = make_float2(o2, o3);
            }
        }
    }
}

// =====================================================================
// Kron edge GEMM via mma.bf16 3-pass:
// out[e,:] = relu(LN( (npj[src]⊗npj[dst]) @ Wk2 + bk2 )), scatter-add to kf[dst].
// Tile: 64 edges x 128 outs, K=400 in 5 chunks of 80 (5 k-steps each).
// Dynamic smem: sa 5120 u32, sb 10240 u32, Ss/Ds 1280 f each, ssrc/sdst 64 each.
// =====================================================================
__global__ __launch_bounds__(256, 2)
void kron_mma(const int* __restrict__ src, const int* __restrict__ dst,
              const uint32_t* __restrict__ Whi, const uint32_t* __restrict__ Wlo,
              const float* __restrict__ bk2,
              const float* __restrict__ lng, const float* __restrict__ lnb,
              int E) {
    extern __shared__ uint32_t dsm[];
    uint32_t* sa = dsm;                       // 5120: hi [0,2560), lo [2560,5120)
    uint32_t* sb = dsm + 5120;                // 10240: hi [0,5120), lo [5120,10240)
    float* Ss = (float*)(dsm + 15360);        // 1280
    float* Ds = Ss + 1280;                    // 1280
    int* ssrc = (int*)(Ds + 1280);            // 64
    int* sdst = ssrc + 64;                    // 64
    __shared__ float red[2][64][2];

    int t = threadIdx.x;
    int lane = t & 31, w = t >> 5;
    int wm = w & 3, wn = w >> 2;
    int e0 = blockIdx.x * 64;

    if (t < 64) {
        int ee = e0 + t; if (ee >= E) ee = E - 1;
        ssrc[t] = src[ee];
        sdst[t] = dst[ee];
    }
    __syncthreads();
    for (int idx = t; idx < 1280; idx += 256) {
        int e = idx / 20, j = idx % 20;
        Ss[idx] = g_npj[ssrc[e] * KP + j];
        Ds[idx] = g_npj[sdst[e] * KP + j];
    }

    float acc[8][4];
    #pragma unroll
    for (int j = 0; j < 8; j++) { acc[j][0]=acc[j][1]=acc[j][2]=acc[j][3]=0.f; }

    int be = t >> 2;     // builder edge 0..63
    int il = t & 3;      // i within chunk (4 i's of 20 j's = 80 k)
    int mt = be >> 4;

    for (int c = 0; c < 5; c++) {
        __syncthreads();
        // ---- A build: products s[e][i]*d[e][j], split to bf16 hi/lo pairs ----
        {
            float sv = Ss[be * 20 + c * 4 + il];
            int ribase = (be >> 3) & 1;
            #pragma unroll
            for (int q = 0; q < 10; q++) {
                float p0 = sv * Ds[be * 20 + 2*q];
                float p1 = sv * Ds[be * 20 + 2*q + 1];
                int kp = il * 10 + q;               // 0..39
                int kstep = kp >> 3;
                int aln = ((be & 7) << 2) + (kp & 3);
                int ri = ribase + (((kp >> 2) & 1) << 1);
                int ai = (((mt * 5 + kstep) * 32 + aln) << 2) + ri;
                sa[ai]        = pkbf(p0, p1);
                sa[2560 + ai] = pkbf(bflo(p0), bflo(p1));
            }
        }
        // ---- B load: Wk2 packed [200][128] ----
        {
            #pragma unroll
            for (int i = 0; i < 20; i++) {
                int idx = t + (i << 8);             // 0..5119
                int kpl = idx >> 7;                 // 0..39
                int n = idx & 127;
                int gidx = (c * 40 + kpl) * 128 + n;
                int nt = n >> 3, kstep = kpl >> 3;
                int bln = ((n & 7) << 2) + (kpl & 3);
                int ri = (kpl >> 2) & 1;
                int bi = (((nt * 5 + kstep) * 32 + bln) << 1) + ri;
                sb[bi]        = Whi[gidx];
                sb[5120 + bi] = Wlo[gidx];
            }
        }
        __syncthreads();
        // ---- compute ----
        #pragma unroll
        for (int ks = 0; ks < 5; ks++) {
            uint4 ah = *(uint4*)&sa[(((wm * 5 + ks) * 32 + lane) << 2)];
            uint4 al = *(uint4*)&sa[2560 + (((wm * 5 + ks) * 32 + lane) << 2)];
            #pragma unroll
            for (int j = 0; j < 8; j++) {
                int nt = wn * 8 + j;
                uint2 bh = *(uint2*)&sb[(((nt * 5 + ks) * 32 + lane) << 1)];
                uint2 bl = *(uint2*)&sb[5120 + (((nt * 5 + ks) * 32 + lane) << 1)];
                MMA_BF16(acc[j], ah, bh);
                MMA_BF16(acc[j], ah, bl);
                MMA_BF16(acc[j], al, bh);
            }
        }
    }

    // ---- epilogue: bias + LN(128) + relu + atomic scatter ----
    #pragma unroll
    for (int j = 0; j < 8; j++) {
        int gc = wn * 64 + j * 8 + ((lane & 3) << 1);
        float b0 = bk2[gc], b1 = bk2[gc + 1];
        acc[j][0] += b0; acc[j][1] += b1; acc[j][2] += b0; acc[j][3] += b1;
    }
    float s_lo=0.f, q_lo=0.f, s_hi=0.f, q_hi=0.f;
    #pragma unroll
    for (int j = 0; j < 8; j++) {
        s_lo += acc[j][0] + acc[j][1];
        q_lo += acc[j][0]*acc[j][0] + acc[j][1]*acc[j][1];
        s_hi += acc[j][2] + acc[j][3];
        q_hi += acc[j][2]*acc[j][2] + acc[j][3]*acc[j][3];
    }
    #pragma unroll
    for (int m = 1; m <= 2; m <<= 1) {
        s_lo += __shfl_xor_sync(0xffffffffu, s_lo, m);
        q_lo += __shfl_xor_sync(0xffffffffu, q_lo, m);
        s_hi += __shfl_xor_sync(0xffffffffu, s_hi, m);
        q_hi += __shfl_xor_sync(0xffffffffu, q_hi, m);
    }
    int rloc = wm * 16 + (lane >> 2);
    if ((lane & 3) == 0) {
        red[wn][rloc][0] = s_lo;     red[wn][rloc][1] = q_lo;
        red[wn][rloc + 8][0] = s_hi; red[wn][rloc + 8][1] = q_hi;
    }
    __syncthreads();
    float ts_lo = s_lo + red[wn ^ 1][rloc][0];
    float tq_lo = q_lo + red[wn ^ 1][rloc][1];
    float ts_hi = s_hi + red[wn ^ 1][rloc + 8][0];
    float tq_hi = q_hi + red[wn ^ 1][rloc + 8][1];
    float mu_lo = ts_lo * (1.f/128.f);
    float mu_hi = ts_hi * (1.f/128.f);
    float rs_lo = rsqrtf(tq_lo * (1.f/128.f) - mu_lo*mu_lo + EPS);
    float rs_hi = rsqrtf(tq_hi * (1.f/128.f) - mu_hi*mu_hi + EPS);

    int ge_lo = e0 + rloc;
    int ge_hi = e0 + rloc + 8;
    int dn_lo = sdst[rloc];
    int dn_hi = sdst[rloc + 8];
    #pragma unroll
    for (int j = 0; j < 8; j++) {
        int gc = wn * 64 + j * 8 + ((lane & 3) << 1);
        float g0 = lng[gc], g1 = lng[gc+1];
        float bb0 = lnb[gc], bb1 = lnb[gc+1];
        if (ge_lo < E) {
            float* p = &g_kf[(size_t)dn_lo * 128 + gc];
            atomicAdd(p,     fmaxf((acc[j][0]-mu_lo)*rs_lo*g0 + bb0, 0.f));
            atomicAdd(p + 1, fmaxf((acc[j][1]-mu_lo)*rs_lo*g1 + bb1, 0.f));
        }
        if (ge_hi < E) {
            float* p = &g_kf[(size_t)dn_hi * 128 + gc];
            atomicAdd(p,     fmaxf((acc[j][2]-mu_hi)*rs_hi*g0 + bb0, 0.f));
            atomicAdd(p + 1, fmaxf((acc[j][3]-mu_hi)*rs_hi*g1 + bb1, 0.f));
        }
    }
}

// ---------------- GRU gates + relu + LN ----------------
__global__ void gates_kernel(const float* __restrict__ x,
                             const float* __restrict__ lng,
                             const float* __restrict__ lnb, int V) {
    int v = blockIdx.x * 4 + (threadIdx.x >> 5);
    if (v >= V) return;
    int lane = threadIdx.x & 31;
    const float* gi = &g_gi[(size_t)v * 384];
    const float* gh = &g_gh[(size_t)v * 384];
    float4 gir = *(const float4*)&gi[(lane << 2)];
    float4 giz = *(const float4*)&gi[128 + (lane << 2)];
    float4 gin = *(const float4*)&gi[256 + (lane << 2)];
    float4 ghr = *(const float4*)&gh[(lane << 2)];
    float4 ghz = *(const float4*)&gh[128 + (lane << 2)];
    float4 ghn = *(const float4*)&gh[256 + (lane << 2)];
    float4 xv  = *(const float4*)&x[(size_t)v * D + (lane << 2)];
    float h[4];
    #pragma unroll
    for (int i = 0; i < 4; i++) {
        float a_r = (&gir.x)[i] + (&ghr.x)[i];
        float a_z = (&giz.x)[i] + (&ghz.x)[i];
        float r = 1.f / (1.f + expf(-a_r));
        float z = 1.f / (1.f + expf(-a_z));
        float n = tanhf((&gin.x)[i] + r * (&ghn.x)[i]);
        float hh = (1.f - z) * n + z * (&xv.x)[i];
        h[i] = fmaxf(hh, 0.f);
    }
    float s = h[0] + h[1] + h[2] + h[3];
    #pragma unroll
    for (int m = 16; m; m >>= 1) s += __shfl_xor_sync(0xffffffffu, s, m);
    float mu = s * (1.f / 128.f);
    float q = 0.f;
    #pragma unroll
    for (int i = 0; i < 4; i++) { float d0 = h[i] - mu; q = fmaf(d0, d0, q); }
    #pragma unroll
    for (int m = 16; m; m >>= 1) q += __shfl_xor_sync(0xffffffffu, q, m);
    float rstd = rsqrtf(q * (1.f / 128.f) + EPS);
    float4 gv = *(const float4*)&lng[lane << 2];
    float4 b2 = *(const float4*)&lnb[lane << 2];
    float4 o;
    o.x = (h[0] - mu) * rstd * gv.x + b2.x;
    o.y = (h[1] - mu) * rstd * gv.y + b2.y;
    o.z = (h[2] - mu) * rstd * gv.z + b2.z;
    o.w = (h[3] - mu) * rstd * gv.w + b2.w;
    *(float4*)&g_gru[(size_t)v * D + (lane << 2)] = o;
}

// ---------------- host ----------------
extern "C" void kernel_launch(void* const* d_in, const int* in_sizes, int n_in,
                              void* d_out, int out_size) {
    const float* node   = (const float*)d_in[0];
    const int*   src    = (const int*)  d_in[1];
    const int*   dst    = (const int*)  d_in[2];
    const float* W_edge = (const float*)d_in[3];
    const float* b_edge = (const float*)d_in[4];
    const float* W_pn   = (const float*)d_in[5];
    const float* b_pn   = (const float*)d_in[6];
    const float* W_ih   = (const float*)d_in[7];
    const float* b_ih   = (const float*)d_in[8];
    const float* W_hh   = (const float*)d_in[9];
    const float* b_hh   = (const float*)d_in[10];
    const float* ln_g   = (const float*)d_in[11];
    const float* ln_b   = (const float*)d_in[12];
    const float* Wk1    = (const float*)d_in[13];
    const float* bk1    = (const float*)d_in[14];
    const float* lnk1_g = (const float*)d_in[15];
    const float* lnk1_b = (const float*)d_in[16];
    const float* Wk2    = (const float*)d_in[17];
    const float* bk2    = (const float*)d_in[18];
    const float* lnk2_g = (const float*)d_in[19];
    const float* lnk2_b = (const float*)d_in[20];
    const float* Wc     = (const float*)d_in[21];
    const float* bc     = (const float*)d_in[22];
    const float* lnc_g  = (const float*)d_in[23];
    const float* lnc_b  = (const float*)d_in[24];
    int V = in_sizes[0] / D;
    int E = in_sizes[1];
    float* out = (float*)d_out;

    float *p_ctx, *p_kf, *p_asum, *p_lmax, *p_hv, *p_gi, *p_gh, *p_gru;
    uint32_t *p_WpnP, *p_WihP, *p_WhhP, *p_WcP, *p_Wk2P;
    cudaGetSymbolAddress((void**)&p_ctx,  g_ctx);
    cudaGetSymbolAddress((void**)&p_kf,   g_kf);
    cudaGetSymbolAddress((void**)&p_asum, g_asum);
    cudaGetSymbolAddress((void**)&p_lmax, g_lmax);
    cudaGetSymbolAddress((void**)&p_hv,   g_hv);
    cudaGetSymbolAddress((void**)&p_gi,   g_gi);
    cudaGetSymbolAddress((void**)&p_gh,   g_gh);
    cudaGetSymbolAddress((void**)&p_gru,  g_gru);
    cudaGetSymbolAddress((void**)&p_WpnP, g_WpnP);
    cudaGetSymbolAddress((void**)&p_WihP, g_WihP);
    cudaGetSymbolAddress((void**)&p_WhhP, g_WhhP);
    cudaGetSymbolAddress((void**)&p_WcP,  g_WcP);
    cudaGetSymbolAddress((void**)&p_Wk2P, g_Wk2P);

    static bool attr_set = false;
    if (!attr_set) {
        cudaFuncSetAttribute(kron_mma, cudaFuncAttributeMaxDynamicSharedMemorySize, 80000);
        attr_set = true;
    }

    // zero accumulators
    {
        int n4 = V * D / 4;
        zero_kernel<<<(n4 + 255) / 256, 256>>>((float4*)p_ctx, n4);
        zero_kernel<<<(n4 + 255) / 256, 256>>>((float4*)p_kf,  n4);
        n4 = V / 4;
        zero_kernel<<<(n4 + 255) / 256, 256>>>((float4*)p_asum, n4);
        zero_kernel<<<(n4 + 255) / 256, 256>>>((float4*)p_lmax, n4);
    }

    // pack weights (bf16 hi/lo pair format)
    pack_w <<<(64  * 128 + 255) / 256, 256>>>(W_pn, 128, 128, p_WpnP, p_WpnP + 64*128);
    pack_wt<<<(64  * 384 + 255) / 256, 256>>>(W_ih, 384, 128, p_WihP, p_WihP + 64*384);
    pack_wt<<<(64  * 384 + 255) / 256, 256>>>(W_hh, 384, 128, p_WhhP, p_WhhP + 64*384);
    pack_w <<<(128 * 128 + 255) / 256, 256>>>(Wc, 256, 128, p_WcP, p_WcP + 128*128);
    pack_w <<<(200 * 128 + 255) / 256, 256>>>(Wk2, 400, 128, p_Wk2P, p_Wk2P + 200*128);

    npj_kernel<<<(V + 3) / 4, 128>>>(node, Wk1, bk1, lnk1_g, lnk1_b, V);
    logits_kernel<<<(E + 3) / 4, 128>>>(node, src, dst, W_edge, b_edge, E);
    expsum_kernel<<<(E + 255) / 256, 256>>>(dst, E);

    int gm = (V + 63) / 64;
    // hv = node @ W_pn + b_pn
    mma_gemm<<<dim3(gm, 1), 256>>>(node, 128, nullptr, 0, 0,
                                   p_WpnP, p_WpnP + 64*128, 128,
                                   b_pn, nullptr, nullptr, p_hv, V);

    // edge kron GEMM + LN + relu + scatter
    kron_mma<<<(E + 63) / 64, 256, 72704>>>(src, dst, p_Wk2P, p_Wk2P + 200*128,
                                            bk2, lnk2_g, lnk2_b, E);

    context_kernel<<<(E + 3) / 4, 128>>>(src, dst, E);

    // gi = relu(ctx) @ W_ih^T + b_ih ; gh = node @ W_hh^T + b_hh
    mma_gemm<<<dim3(gm, 3), 256>>>(p_ctx, 128, nullptr, 0, 1,
                                   p_WihP, p_WihP + 64*384, 384,
                                   b_ih, nullptr, nullptr, p_gi, V);
    mma_gemm<<<dim3(gm, 3), 256>>>(node, 128, nullptr, 0, 0,
                                   p_WhhP, p_WhhP + 64*384, 384,
                                   b_hh, nullptr, nullptr, p_gh, V);

    gates_kernel<<<(V + 3) / 4, 128>>>(node, ln_g, ln_b, V);

    // out = relu(LN(cat(gru, kron_feat) @ Wc + bc))
    mma_gemm<<<dim3(gm, 1), 256>>>(p_gru, 128, p_kf, 128, 0,
                                   p_WcP, p_WcP + 128*128, 128,
                                   bc, lnc_g, lnc_b, out, V);
}

// round 3
// speedup vs baseline: 2.0294x; 1.4017x over previous
#include <cuda_runtime.h>
#include <cuda_bf16.h>
#include <math.h>
#include <stdint.h>

#define D     128
#define KP    20
#define OUTD  128
#define VMAX  100000
#define EMAX  400000
#define EPS   1e-5f
#define NBMAX 1563   // (VMAX+63)/64

// ---------------- scratch (device globals; no allocations) ----------------
__device__ float g_npj  [VMAX * KP];
__device__ float g_logit[EMAX];
__device__ float g_aexp [EMAX];
__device__ float g_lmax [VMAX];
__device__ float g_asum [VMAX];
__device__ float g_hv   [VMAX * D];
__device__ float g_ctx  [VMAX * D];
__device__ float g_kf   [VMAX * OUTD];
__device__ float g_gi   [VMAX * 3 * D];
__device__ float g_gh   [VMAX * 3 * D];
__device__ float g_gru  [VMAX * D];

// fragment-ordered bf16 hi/lo weight streams
__device__ uint32_t g_WpnS[1 * 4 * 4096];
__device__ uint32_t g_WihS[3 * 4 * 4096];
__device__ uint32_t g_WhhS[3 * 4 * 4096];
__device__ uint32_t g_WcS [1 * 8 * 4096];
__device__ uint32_t g_Wk2S[5 * 10240];

// fragment-ordered bf16 hi/lo activation streams
__device__ uint32_t g_Anode[(size_t)NBMAX * 4 * 4096];
__device__ uint32_t g_Actx [(size_t)NBMAX * 4 * 4096];
__device__ uint32_t g_Acat [(size_t)NBMAX * 8 * 4096];

// ---------------- fast bf16 hi/lo split (truncation) ----------------
// hi = top-16-bits of a (exact bf16), lo = a - hi (exact fp32), lo rounded RN.
__device__ __forceinline__ void split_pair(float a0, float a1,
                                           uint32_t& hi, uint32_t& lo) {
    uint32_t b0 = __float_as_uint(a0), b1 = __float_as_uint(a1);
    uint32_t hp;
    asm("prmt.b32 %0, %1, %2, 0x7632;" : "=r"(hp) : "r"(b0), "r"(b1));
    float l0 = a0 - __uint_as_float(b0 & 0xffff0000u);
    float l1 = a1 - __uint_as_float(b1 & 0xffff0000u);
    __nv_bfloat162 lp = __floats2bfloat162_rn(l0, l1);
    hi = hp;
    lo = *(uint32_t*)&lp;
}

#define MMA_BF16(c, A, B) asm volatile( \
    "mma.sync.aligned.m16n8k16.row.col.f32.bf16.bf16.f32 " \
    "{%0,%1,%2,%3}, {%4,%5,%6,%7}, {%8,%9}, {%0,%1,%2,%3};\n" \
    : "+f"(c[0]), "+f"(c[1]), "+f"(c[2]), "+f"(c[3]) \
    : "r"(A.x), "r"(A.y), "r"(A.z), "r"(A.w), "r"(B.x), "r"(B.y))

// ---------------- utility kernels ----------------
__global__ void zero_kernel(float4* p, int n4) {
    int i = blockIdx.x * blockDim.x + threadIdx.x;
    if (i < n4) p[i] = make_float4(0.f, 0.f, 0.f, 0.f);
}

// pack weights into fragment stream: per (ny, chunk): hi[0,2048) lo[2048,4096)
// transp=0: W[k][Ntot]; transp=1: W stored [Ntot_rows][K] (out-major)
__global__ void pack_w_frag(const float* __restrict__ W, int K, int Ntot,
                            int transp, uint32_t* __restrict__ out) {
    int idx = blockIdx.x * blockDim.x + threadIdx.x;
    int total = (K / 2) * Ntot;
    if (idx >= total) return;
    int kp = idx / Ntot, n = idx - kp * Ntot;
    int k0 = 2 * kp;
    float w0, w1;
    if (transp) { w0 = W[n * K + k0]; w1 = W[n * K + k0 + 1]; }
    else        { w0 = W[k0 * Ntot + n]; w1 = W[(k0 + 1) * Ntot + n]; }
    int c = kp >> 4, kpl = kp & 15;
    int ny = n >> 7, nl = n & 127;
    int bi = ((((nl >> 3) * 2 + (kpl >> 3)) * 32 + ((nl & 7) << 2) + (kpl & 3)) << 1)
             + ((kpl >> 2) & 1);
    size_t base = ((size_t)(ny * (K >> 5) + c)) << 12;
    uint32_t hi, lo;
    split_pair(w0, w1, hi, lo);
    out[base + bi] = hi;
    out[base + 2048 + bi] = lo;
}

// Wk2 [400][128] -> kron stream: per chunk(5): hi[0,5120) lo[5120,10240)
__global__ void pack_wk2(const float* __restrict__ W, uint32_t* __restrict__ out) {
    int idx = blockIdx.x * blockDim.x + threadIdx.x;  // over 200*128
    if (idx >= 200 * 128) return;
    int kp = idx >> 7, n = idx & 127;
    float w0 = W[(2 * kp) * 128 + n];
    float w1 = W[(2 * kp + 1) * 128 + n];
    int c = kp / 40, kpl = kp - c * 40;
    int bi = ((((n >> 3) * 5 + (kpl >> 3)) * 32 + ((n & 7) << 2) + (kpl & 3)) << 1)
             + ((kpl >> 2) & 1);
    uint32_t hi, lo;
    split_pair(w0, w1, hi, lo);
    out[c * 10240 + bi] = hi;
    out[c * 10240 + 5120 + bi] = lo;
}

// pack fp32 activation [V, K0(+K1)] into fragment stream, optional relu.
// stream: per (mblock, chunk): 4096 u32, hi[0,2048) lo[2048,4096)
__global__ void pack_act(const float* __restrict__ X0, int K0,
                         const float* __restrict__ X1, int K1, int relu,
                         uint32_t* __restrict__ out, int V) {
    int t = threadIdx.x;
    int mb = blockIdx.x;
    int K = K0 + K1;
    int Kch = K >> 5;
    size_t obase = ((size_t)mb * Kch) << 12;
    for (int it = 0; it < Kch * 8; it++) {
        int c = it >> 3;
        int idx = ((it & 7) << 8) + t;      // 0..2047 within chunk
        int ri = idx & 3;
        int lane = (idx >> 2) & 31;
        int kstep = (idx >> 7) & 1;
        int mt = idx >> 8;
        int row = mb * 64 + mt * 16 + (ri & 1) * 8 + (lane >> 2);
        if (row >= V) row = V - 1;
        int kp = kstep * 8 + ((ri >> 1) << 2) + (lane & 3);
        int k = c * 32 + kp * 2;
        float2 a;
        if (k < K0) a = *(const float2*)&X0[(size_t)row * K0 + k];
        else        a = *(const float2*)&X1[(size_t)row * K1 + (k - K0)];
        if (relu) { a.x = fmaxf(a.x, 0.f); a.y = fmaxf(a.y, 0.f); }
        uint32_t hi, lo;
        split_pair(a.x, a.y, hi, lo);
        size_t base = obase + ((size_t)c << 12);
        out[base + idx] = hi;
        out[base + 2048 + idx] = lo;
    }
}

// ---------------- npj = relu(LN(x @ Wk1 + bk1)), [V,20] ----------------
__global__ void npj_kernel(const float* __restrict__ x,
                           const float* __restrict__ Wk1,
                           const float* __restrict__ bk1,
                           const float* __restrict__ g,
                           const float* __restrict__ b, int V) {
    __shared__ float xs[4][D];
    int warp = threadIdx.x >> 5, lane = threadIdx.x & 31;
    int v  = blockIdx.x * 4 + warp;
    int vc = v < V ? v : V - 1;
    *(float4*)&xs[warp][lane << 2] = *(const float4*)&x[vc * D + (lane << 2)];
    __syncwarp();
    float y = 0.f;
    if (lane < KP) {
        #pragma unroll 8
        for (int k = 0; k < D; k++) y = fmaf(xs[warp][k], Wk1[k * KP + lane], y);
        y += bk1[lane];
    }
    float s = (lane < KP) ? y : 0.f;
    #pragma unroll
    for (int m = 16; m; m >>= 1) s += __shfl_xor_sync(0xffffffffu, s, m);
    float mu = s * (1.f / KP);
    float dv = (lane < KP) ? (y - mu) * (y - mu) : 0.f;
    #pragma unroll
    for (int m = 16; m; m >>= 1) dv += __shfl_xor_sync(0xffffffffu, dv, m);
    float rstd = rsqrtf(dv * (1.f / KP) + EPS);
    if (v < V && lane < KP) {
        float val = (y - mu) * rstd * g[lane] + b[lane];
        g_npj[v * KP + lane] = fmaxf(val, 0.f);
    }
}

// ---------------- edge logits + segment max ----------------
__global__ void logits_kernel(const float* __restrict__ x,
                              const int* __restrict__ src,
                              const int* __restrict__ dst,
                              const float* __restrict__ We,
                              const float* __restrict__ be, int E) {
    int e = blockIdx.x * 4 + (threadIdx.x >> 5);
    if (e >= E) return;
    int lane = threadIdx.x & 31;
    int sn = src[e], dn = dst[e];
    float4 xd = *(const float4*)&x[dn * D + (lane << 2)];
    float4 w1 = *(const float4*)&We[lane << 2];
    float4 xv = *(const float4*)&x[sn * D + (lane << 2)];
    float4 w2 = *(const float4*)&We[D + (lane << 2)];
    float p = xd.x * w1.x + xd.y * w1.y + xd.z * w1.z + xd.w * w1.w
            + xv.x * w2.x + xv.y * w2.y + xv.z * w2.z + xv.w * w2.w;
    #pragma unroll
    for (int m = 16; m; m >>= 1) p += __shfl_xor_sync(0xffffffffu, p, m);
    if (lane == 0) {
        float lg = fmaxf(p + be[0], 0.f);
        g_logit[e] = lg;
        atomicMax((int*)&g_lmax[dn], __float_as_int(lg));  // valid: lg >= 0
    }
}

// ---------------- a = exp(logit - lmax[dst]); asum += a ----------------
__global__ void expsum_kernel(const int* __restrict__ dst, int E) {
    int e = blockIdx.x * blockDim.x + threadIdx.x;
    if (e >= E) return;
    int dn = dst[e];
    float a = expf(g_logit[e] - g_lmax[dn]);
    g_aexp[e] = a;
    atomicAdd(&g_asum[dn], a);
}

// ---------------- context scatter: ctx[dst] += hv[src] * (a/asum[dst]) ----
__global__ void context_kernel(const int* __restrict__ src,
                               const int* __restrict__ dst, int E) {
    int e = blockIdx.x * 4 + (threadIdx.x >> 5);
    if (e >= E) return;
    int lane = threadIdx.x & 31;
    int sn = src[e], dn = dst[e];
    float coef = g_aexp[e] / g_asum[dn];
    float4 h = *(const float4*)&g_hv[sn * D + (lane << 2)];
    float* p = &g_ctx[dn * D + (lane << 2)];
    atomicAdd(p + 0, h.x * coef);
    atomicAdd(p + 1, h.y * coef);
    atomicAdd(p + 2, h.z * coef);
    atomicAdd(p + 3, h.w * coef);
}

// =====================================================================
// Node GEMM via mma.bf16 3-pass, A and B pre-packed fragment streams.
// Tile M=64 x N=128, K chunk 32. 8 warps: wm = w&3 (m16 group), wn = w>>2.
// =====================================================================
__global__ __launch_bounds__(256)
void mma_gemm(const uint32_t* __restrict__ As, const uint32_t* __restrict__ Bs,
              int Kchunks, int Ntot,
              const float* __restrict__ bias,
              const float* __restrict__ lng, const float* __restrict__ lnb,
              float* __restrict__ out, int V) {
    __shared__ uint32_t sa[4096];   // hi [0,2048) lo [2048,4096)
    __shared__ uint32_t sb[4096];
    __shared__ float red[2][64][2];

    int t = threadIdx.x;
    int lane = t & 31, w = t >> 5;
    int wm = w & 3, wn = w >> 2;
    int row0 = blockIdx.x * 64;
    int nb = blockIdx.y * 128;

    float acc[8][4];
    #pragma unroll
    for (int j = 0; j < 8; j++) { acc[j][0]=acc[j][1]=acc[j][2]=acc[j][3]=0.f; }

    const uint4* asrc = (const uint4*)(As + (((size_t)blockIdx.x * Kchunks) << 12));
    const uint4* bsrc = (const uint4*)(Bs + (((size_t)blockIdx.y * Kchunks) << 12));

    for (int c = 0; c < Kchunks; c++) {
        __syncthreads();
        #pragma unroll
        for (int i = 0; i < 4; i++) {
            ((uint4*)sa)[t + (i << 8)] = asrc[(c << 10) + t + (i << 8)];
            ((uint4*)sb)[t + (i << 8)] = bsrc[(c << 10) + t + (i << 8)];
        }
        __syncthreads();
        #pragma unroll
        for (int ks = 0; ks < 2; ks++) {
            uint4 ah = ((const uint4*)sa)[(wm * 2 + ks) * 32 + lane];
            uint4 al = ((const uint4*)sa)[512 + (wm * 2 + ks) * 32 + lane];
            #pragma unroll
            for (int j = 0; j < 8; j++) {
                int nt = wn * 8 + j;
                uint2 bh = ((const uint2*)sb)[(nt * 2 + ks) * 32 + lane];
                uint2 bl = ((const uint2*)sb)[1024 + (nt * 2 + ks) * 32 + lane];
                MMA_BF16(acc[j], ah, bh);
                MMA_BF16(acc[j], ah, bl);
                MMA_BF16(acc[j], al, bh);
            }
        }
    }

    int rl = row0 + wm * 16 + (lane >> 2);
    int rh = rl + 8;
    #pragma unroll
    for (int j = 0; j < 8; j++) {
        int gc = nb + wn * 64 + j * 8 + ((lane & 3) << 1);
        float b0 = bias[gc], b1 = bias[gc + 1];
        acc[j][0] += b0; acc[j][1] += b1; acc[j][2] += b0; acc[j][3] += b1;
    }
    if (lng == nullptr) {
        #pragma unroll
        for (int j = 0; j < 8; j++) {
            int gc = nb + wn * 64 + j * 8 + ((lane & 3) << 1);
            if (rl < V) *(float2*)&out[(size_t)rl * Ntot + gc] = make_float2(acc[j][0], acc[j][1]);
            if (rh < V) *(float2*)&out[(size_t)rh * Ntot + gc] = make_float2(acc[j][2], acc[j][3]);
        }
    } else {
        float s_lo=0.f, q_lo=0.f, s_hi=0.f, q_hi=0.f;
        #pragma unroll
        for (int j = 0; j < 8; j++) {
            s_lo += acc[j][0] + acc[j][1];
            q_lo += acc[j][0]*acc[j][0] + acc[j][1]*acc[j][1];
            s_hi += acc[j][2] + acc[j][3];
            q_hi += acc[j][2]*acc[j][2] + acc[j][3]*acc[j][3];
        }
        #pragma unroll
        for (int m = 1; m <= 2; m <<= 1) {
            s_lo += __shfl_xor_sync(0xffffffffu, s_lo, m);
            q_lo += __shfl_xor_sync(0xffffffffu, q_lo, m);
            s_hi += __shfl_xor_sync(0xffffffffu, s_hi, m);
            q_hi += __shfl_xor_sync(0xffffffffu, q_hi, m);
        }
        int rloc = wm * 16 + (lane >> 2);
        if ((lane & 3) == 0) {
            red[wn][rloc][0] = s_lo;   red[wn][rloc][1] = q_lo;
            red[wn][rloc+8][0] = s_hi; red[wn][rloc+8][1] = q_hi;
        }
        __syncthreads();
        float ts_lo = s_lo + red[wn ^ 1][rloc][0];
        float tq_lo = q_lo + red[wn ^ 1][rloc][1];
        float ts_hi = s_hi + red[wn ^ 1][rloc + 8][0];
        float tq_hi = q_hi + red[wn ^ 1][rloc + 8][1];
        float mu_lo = ts_lo * (1.f/128.f);
        float mu_hi = ts_hi * (1.f/128.f);
        float rs_lo = rsqrtf(tq_lo * (1.f/128.f) - mu_lo*mu_lo + EPS);
        float rs_hi = rsqrtf(tq_hi * (1.f/128.f) - mu_hi*mu_hi + EPS);
        #pragma unroll
        for (int j = 0; j < 8; j++) {
            int gc = wn * 64 + j * 8 + ((lane & 3) << 1);
            float g0 = lng[gc], g1 = lng[gc+1];
            float bb0 = lnb[gc], bb1 = lnb[gc+1];
            if (rl < V) {
                float o0 = fmaxf((acc[j][0]-mu_lo)*rs_lo*g0 + bb0, 0.f);
                float o1 = fmaxf((acc[j][1]-mu_lo)*rs_lo*g1 + bb1, 0.f);
                *(float2*)&out[(size_t)rl * 128 + gc] = make_float2(o0, o1);
            }
            if (rh < V) {
                float o2 = fmaxf((acc[j][2]-mu_hi)*rs_hi*g0 + bb0, 0.f);
                float o3 = fmaxf((acc[j][3]-mu_hi)*rs_hi*g1 + bb1, 0.f);
                *(float2*)&out[(size_t)rh * 128 + gc] = make_float2(o2, o3);
            }
        }
    }
}

// =====================================================================
// Kron edge GEMM, M=128 edges x N=128 outs, K=400 (5 chunks of 80).
// 8 warps: wm = w&3 (32-row group), wn = w>>2 (64-col half).
// dynamic smem: sa 10240 u32 (hi/lo), sb 10240 u32, Ss 2560 f, Ds 2560 f.
// =====================================================================
__global__ __launch_bounds__(256, 2)
void kron_mma(const int* __restrict__ src, const int* __restrict__ dst,
              const uint32_t* __restrict__ Wk2S,
              const float* __restrict__ bk2,
              const float* __restrict__ lng, const float* __restrict__ lnb,
              int E) {
    extern __shared__ uint32_t dsm[];
    uint32_t* sa = dsm;               // 10240: hi [0,5120) lo [5120,10240)
    uint32_t* sb = dsm + 10240;       // 10240: hi [0,5120) lo [5120,10240)
    float* Ss = (float*)(dsm + 20480);   // 128*20
    float* Ds = Ss + 2560;               // 128*20
    __shared__ int ssrc[128], sdst[128];
    __shared__ float red[2][128][2];

    int t = threadIdx.x;
    int lane = t & 31, w = t >> 5;
    int wm = w & 3, wn = w >> 2;
    int e0 = blockIdx.x * 128;

    if (t < 128) {
        int ee = e0 + t; if (ee >= E) ee = E - 1;
        ssrc[t] = src[ee];
        sdst[t] = dst[ee];
    }
    __syncthreads();
    for (int idx = t; idx < 640; idx += 256) {
        int e = idx / 5, q = idx - e * 5;
        ((float4*)Ss)[idx] = *(const float4*)&g_npj[ssrc[e] * KP + q * 4];
        ((float4*)Ds)[idx] = *(const float4*)&g_npj[sdst[e] * KP + q * 4];
    }

    float acc[2][8][4];
    #pragma unroll
    for (int r = 0; r < 2; r++)
        #pragma unroll
        for (int j = 0; j < 8; j++) { acc[r][j][0]=acc[r][j][1]=acc[r][j][2]=acc[r][j][3]=0.f; }

    int be = t >> 1, ih = t & 1;
    int amt = be >> 4;
    int ribase = (be >> 3) & 1;
    int alnb = (be & 7) << 2;

    for (int c = 0; c < 5; c++) {
        __syncthreads();
        // ---- A build: products split hi/lo (fast trunc split) ----
        {
            const float* ds = &Ds[be * 20];
            #pragma unroll
            for (int iv = 0; iv < 2; iv++) {
                int il = ih * 2 + iv;
                float sv = Ss[be * 20 + c * 4 + il];
                #pragma unroll
                for (int q = 0; q < 10; q++) {
                    float2 d = *(const float2*)&ds[2 * q];
                    float p0 = sv * d.x, p1 = sv * d.y;
                    int kp = il * 10 + q;
                    int ai = (((amt * 5 + (kp >> 3)) * 32 + alnb + (kp & 3)) << 2)
                             + ribase + (((kp >> 2) & 1) << 1);
                    uint32_t hi, lo;
                    split_pair(p0, p1, hi, lo);
                    sa[ai] = hi;
                    sa[5120 + ai] = lo;
                }
            }
        }
        // ---- B copy (pre-ordered stream) ----
        {
            const uint4* bsrc = (const uint4*)(Wk2S + c * 10240);
            #pragma unroll
            for (int i = 0; i < 10; i++)
                ((uint4*)sb)[t + (i << 8)] = bsrc[t + (i << 8)];
        }
        __syncthreads();
        // ---- compute ----
        #pragma unroll
        for (int ks = 0; ks < 5; ks++) {
            uint4 ah0 = ((const uint4*)sa)[((wm * 2 + 0) * 5 + ks) * 32 + lane];
            uint4 al0 = ((const uint4*)sa)[1280 + ((wm * 2 + 0) * 5 + ks) * 32 + lane];
            uint4 ah1 = ((const uint4*)sa)[((wm * 2 + 1) * 5 + ks) * 32 + lane];
            uint4 al1 = ((const uint4*)sa)[1280 + ((wm * 2 + 1) * 5 + ks) * 32 + lane];
            #pragma unroll
            for (int j = 0; j < 8; j++) {
                int nt = wn * 8 + j;
                uint2 bh = ((const uint2*)sb)[(nt * 5 + ks) * 32 + lane];
                uint2 bl = ((const uint2*)sb)[2560 + (nt * 5 + ks) * 32 + lane];
                MMA_BF16(acc[0][j], ah0, bh);
                MMA_BF16(acc[0][j], ah0, bl);
                MMA_BF16(acc[0][j], al0, bh);
                MMA_BF16(acc[1][j], ah1, bh);
                MMA_BF16(acc[1][j], ah1, bl);
                MMA_BF16(acc[1][j], al1, bh);
            }
        }
    }

    // ---- epilogue: bias + LN(128) + relu + atomic scatter ----
    #pragma unroll
    for (int r = 0; r < 2; r++)
        #pragma unroll
        for (int j = 0; j < 8; j++) {
            int gc = wn * 64 + j * 8 + ((lane & 3) << 1);
            float b0 = bk2[gc], b1 = bk2[gc + 1];
            acc[r][j][0] += b0; acc[r][j][1] += b1;
            acc[r][j][2] += b0; acc[r][j][3] += b1;
        }
    float sum[2][2], sq[2][2];
    #pragma unroll
    for (int r = 0; r < 2; r++) {
        float s_lo=0.f, q_lo=0.f, s_hi=0.f, q_hi=0.f;
        #pragma unroll
        for (int j = 0; j < 8; j++) {
            s_lo += acc[r][j][0] + acc[r][j][1];
            q_lo += acc[r][j][0]*acc[r][j][0] + acc[r][j][1]*acc[r][j][1];
            s_hi += acc[r][j][2] + acc[r][j][3];
            q_hi += acc[r][j][2]*acc[r][j][2] + acc[r][j][3]*acc[r][j][3];
        }
        #pragma unroll
        for (int m = 1; m <= 2; m <<= 1) {
            s_lo += __shfl_xor_sync(0xffffffffu, s_lo, m);
            q_lo += __shfl_xor_sync(0xffffffffu, q_lo, m);
            s_hi += __shfl_xor_sync(0xffffffffu, s_hi, m);
            q_hi += __shfl_xor_sync(0xffffffffu, q_hi, m);
        }
        sum[r][0] = s_lo; sq[r][0] = q_lo;
        sum[r][1] = s_hi; sq[r][1] = q_hi;
        if ((lane & 3) == 0) {
            int rloc = wm * 32 + r * 16 + (lane >> 2);
            red[wn][rloc][0] = s_lo;     red[wn][rloc][1] = q_lo;
            red[wn][rloc + 8][0] = s_hi; red[wn][rloc + 8][1] = q_hi;
        }
    }
    __syncthreads();
    #pragma unroll
    for (int r = 0; r < 2; r++) {
        #pragma unroll
        for (int h = 0; h < 2; h++) {
            int rloc = wm * 32 + r * 16 + h * 8 + (lane >> 2);
            float ts = sum[r][h] + red[wn ^ 1][rloc][0];
            float tq = sq[r][h] + red[wn ^ 1][rloc][1];
            float mu = ts * (1.f / 128.f);
            float rs = rsqrtf(tq * (1.f / 128.f) - mu * mu + EPS);
            int ge = e0 + rloc;
            if (ge < E) {
                int dn = sdst[rloc];
                #pragma unroll
                for (int j = 0; j < 8; j++) {
                    int gc = wn * 64 + j * 8 + ((lane & 3) << 1);
                    float g0 = lng[gc], g1 = lng[gc + 1];
                    float bb0 = lnb[gc], bb1 = lnb[gc + 1];
                    float* p = &g_kf[(size_t)dn * 128 + gc];
                    atomicAdd(p,     fmaxf((acc[r][j][2*h  ]-mu)*rs*g0 + bb0, 0.f));
                    atomicAdd(p + 1, fmaxf((acc[r][j][2*h+1]-mu)*rs*g1 + bb1, 0.f));
                }
            }
        }
    }
}

// ---------------- GRU gates + relu + LN ----------------
__global__ void gates_kernel(const float* __restrict__ x,
                             const float* __restrict__ lng,
                             const float* __restrict__ lnb, int V) {
    int v = blockIdx.x * 4 + (threadIdx.x >> 5);
    if (v >= V) return;
    int lane = threadIdx.x & 31;
    const float* gi = &g_gi[(size_t)v * 384];
    const float* gh = &g_gh[(size_t)v * 384];
    float4 gir = *(const float4*)&gi[(lane << 2)];
    float4 giz = *(const float4*)&gi[128 + (lane << 2)];
    float4 gin = *(const float4*)&gi[256 + (lane << 2)];
    float4 ghr = *(const float4*)&gh[(lane << 2)];
    float4 ghz = *(const float4*)&gh[128 + (lane << 2)];
    float4 ghn = *(const float4*)&gh[256 + (lane << 2)];
    float4 xv  = *(const float4*)&x[(size_t)v * D + (lane << 2)];
    float h[4];
    #pragma unroll
    for (int i = 0; i < 4; i++) {
        float a_r = (&gir.x)[i] + (&ghr.x)[i];
        float a_z = (&giz.x)[i] + (&ghz.x)[i];
        float r = 1.f / (1.f + expf(-a_r));
        float z = 1.f / (1.f + expf(-a_z));
        float n = tanhf((&gin.x)[i] + r * (&ghn.x)[i]);
        float hh = (1.f - z) * n + z * (&xv.x)[i];
        h[i] = fmaxf(hh, 0.f);
    }
    float s = h[0] + h[1] + h[2] + h[3];
    #pragma unroll
    for (int m = 16; m; m >>= 1) s += __shfl_xor_sync(0xffffffffu, s, m);
    float mu = s * (1.f / 128.f);
    float q = 0.f;
    #pragma unroll
    for (int i = 0; i < 4; i++) { float d0 = h[i] - mu; q = fmaf(d0, d0, q); }
    #pragma unroll
    for (int m = 16; m; m >>= 1) q += __shfl_xor_sync(0xffffffffu, q, m);
    float rstd = rsqrtf(q * (1.f / 128.f) + EPS);
    float4 gv = *(const float4*)&lng[lane << 2];
    float4 b2 = *(const float4*)&lnb[lane << 2];
    float4 o;
    o.x = (h[0] - mu) * rstd * gv.x + b2.x;
    o.y = (h[1] - mu) * rstd * gv.y + b2.y;
    o.z = (h[2] - mu) * rstd * gv.z + b2.z;
    o.w = (h[3] - mu) * rstd * gv.w + b2.w;
    *(float4*)&g_gru[(size_t)v * D + (lane << 2)] = o;
}

// ---------------- host ----------------
extern "C" void kernel_launch(void* const* d_in, const int* in_sizes, int n_in,
                              void* d_out, int out_size) {
    const float* node   = (const float*)d_in[0];
    const int*   src    = (const int*)  d_in[1];
    const int*   dst    = (const int*)  d_in[2];
    const float* W_edge = (const float*)d_in[3];
    const float* b_edge = (const float*)d_in[4];
    const float* W_pn   = (const float*)d_in[5];
    const float* b_pn   = (const float*)d_in[6];
    const float* W_ih   = (const float*)d_in[7];
    const float* b_ih   = (const float*)d_in[8];
    const float* W_hh   = (const float*)d_in[9];
    const float* b_hh   = (const float*)d_in[10];
    const float* ln_g   = (const float*)d_in[11];
    const float* ln_b   = (const float*)d_in[12];
    const float* Wk1    = (const float*)d_in[13];
    const float* bk1    = (const float*)d_in[14];
    const float* lnk1_g = (const float*)d_in[15];
    const float* lnk1_b = (const float*)d_in[16];
    const float* Wk2    = (const float*)d_in[17];
    const float* bk2    = (const float*)d_in[18];
    const float* lnk2_g = (const float*)d_in[19];
    const float* lnk2_b = (const float*)d_in[20];
    const float* Wc     = (const float*)d_in[21];
    const float* bc     = (const float*)d_in[22];
    const float* lnc_g  = (const float*)d_in[23];
    const float* lnc_b  = (const float*)d_in[24];
    int V = in_sizes[0] / D;
    int E = in_sizes[1];
    float* out = (float*)d_out;

    float *p_ctx, *p_kf, *p_asum, *p_lmax, *p_hv, *p_gi, *p_gh, *p_gru;
    uint32_t *p_WpnS, *p_WihS, *p_WhhS, *p_WcS, *p_Wk2S;
    uint32_t *p_Anode, *p_Actx, *p_Acat;
    cudaGetSymbolAddress((void**)&p_ctx,   g_ctx);
    cudaGetSymbolAddress((void**)&p_kf,    g_kf);
    cudaGetSymbolAddress((void**)&p_asum,  g_asum);
    cudaGetSymbolAddress((void**)&p_lmax,  g_lmax);
    cudaGetSymbolAddress((void**)&p_hv,    g_hv);
    cudaGetSymbolAddress((void**)&p_gi,    g_gi);
    cudaGetSymbolAddress((void**)&p_gh,    g_gh);
    cudaGetSymbolAddress((void**)&p_gru,   g_gru);
    cudaGetSymbolAddress((void**)&p_WpnS,  g_WpnS);
    cudaGetSymbolAddress((void**)&p_WihS,  g_WihS);
    cudaGetSymbolAddress((void**)&p_WhhS,  g_WhhS);
    cudaGetSymbolAddress((void**)&p_WcS,   g_WcS);
    cudaGetSymbolAddress((void**)&p_Wk2S,  g_Wk2S);
    cudaGetSymbolAddress((void**)&p_Anode, g_Anode);
    cudaGetSymbolAddress((void**)&p_Actx,  g_Actx);
    cudaGetSymbolAddress((void**)&p_Acat,  g_Acat);

    static bool attr_set = false;
    if (!attr_set) {
        cudaFuncSetAttribute(kron_mma, cudaFuncAttributeMaxDynamicSharedMemorySize, 103000);
        attr_set = true;
    }

    int NBv = (V + 63) / 64;

    // zero accumulators
    {
        int n4 = V * D / 4;
        zero_kernel<<<(n4 + 255) / 256, 256>>>((float4*)p_ctx, n4);
        zero_kernel<<<(n4 + 255) / 256, 256>>>((float4*)p_kf,  n4);
        n4 = V / 4;
        zero_kernel<<<(n4 + 255) / 256, 256>>>((float4*)p_asum, n4);
        zero_kernel<<<(n4 + 255) / 256, 256>>>((float4*)p_lmax, n4);
    }

    // pack weights into fragment streams
    pack_w_frag<<<(64 * 128 + 255) / 256, 256>>>(W_pn, 128, 128, 0, p_WpnS);
    pack_w_frag<<<(64 * 384 + 255) / 256, 256>>>(W_ih, 128, 384, 1, p_WihS);
    pack_w_frag<<<(64 * 384 + 255) / 256, 256>>>(W_hh, 128, 384, 1, p_WhhS);
    pack_w_frag<<<(128 * 128 + 255) / 256, 256>>>(Wc, 256, 128, 0, p_WcS);
    pack_wk2<<<(200 * 128 + 255) / 256, 256>>>(Wk2, p_Wk2S);

    // pack node activations
    pack_act<<<NBv, 256>>>(node, 128, nullptr, 0, 0, p_Anode, V);

    npj_kernel<<<(V + 3) / 4, 128>>>(node, Wk1, bk1, lnk1_g, lnk1_b, V);
    logits_kernel<<<(E + 3) / 4, 128>>>(node, src, dst, W_edge, b_edge, E);
    expsum_kernel<<<(E + 255) / 256, 256>>>(dst, E);

    // hv = node @ W_pn + b_pn
    mma_gemm<<<dim3(NBv, 1), 256>>>(p_Anode, p_WpnS, 4, 128,
                                    b_pn, nullptr, nullptr, p_hv, V);

    // edge kron GEMM + LN + relu + scatter
    kron_mma<<<(E + 127) / 128, 256, 102400>>>(src, dst, p_Wk2S,
                                               bk2, lnk2_g, lnk2_b, E);

    context_kernel<<<(E + 3) / 4, 128>>>(src, dst, E);

    // pack relu(ctx)
    pack_act<<<NBv, 256>>>(p_ctx, 128, nullptr, 0, 1, p_Actx, V);

    // gi = relu(ctx) @ W_ih^T + b_ih ; gh = node @ W_hh^T + b_hh
    mma_gemm<<<dim3(NBv, 3), 256>>>(p_Actx, p_WihS, 4, 384,
                                    b_ih, nullptr, nullptr, p_gi, V);
    mma_gemm<<<dim3(NBv, 3), 256>>>(p_Anode, p_WhhS, 4, 384,
                                    b_hh, nullptr, nullptr, p_gh, V);

    gates_kernel<<<(V + 3) / 4, 128>>>(node, ln_g, ln_b, V);

    // pack cat(gru, kf)
    pack_act<<<NBv, 256>>>(p_gru, 128, p_kf, 128, 0, p_Acat, V);

    // out = relu(LN(cat @ Wc + bc))
    mma_gemm<<<dim3(NBv, 1), 256>>>(p_Acat, p_WcS, 8, 128,
                                    bc, lnc_g, lnc_b, out, V);
}